// round 15
// baseline (speedup 1.0000x reference)
#include <cuda_runtime.h>
#include <cuda_fp16.h>
#include <cstdint>

// ---------------------------------------------------------------------------
// Problem constants
// ---------------------------------------------------------------------------
#define BB 16
#define NQS 2048
#define NKS 2048
#define DHD 128
#define OUT_ELEMS (BB * NQS * DHD)                 // 4194304
#define ATTN_ELEMS ((long long)BB * NQS * NKS)     // 67108864

#define TWO_PI_F  6.283185307179586f
#define INV2W2_F  0.8105694691387022f   // 1/(2*(pi/4)^2)
#define SCALE_F   0.08838834764831843f  // 1/sqrt(128)

#define NTHR 256      // 8 warps; 2 CTAs co-resident per SM
#define QT   64       // q rows per CTA
#define KT   32       // keys per iteration
#define NIT  64       // 2048 / 32

// ---------------------------------------------------------------------------
// SMEM layout (per CTA, 66816 B => 2 CTAs/SM). Strides bank-checked:
//  272B (68 w) tiles: ldmatrix phases cover all 32 banks (proven R8);
//  80B (20 w) P tile: row banks {0,20,8,28,16,4,24,12}+c — bijective.
// ---------------------------------------------------------------------------
#define SM_GATE  0         // 2048 f32                          8192 B
#define SM_RS    8192      // 64 f32 inv rowsum                  256 B
#define SM_RSP   8448      // 4 x 64 f32 partials               1024 B
#define SM_Q     9472      // 64 x 136 fp16 (QSTR=272)         17408 B
#define SM_K0    26880     // 2 x (32 x 136 fp16)              17408 B
#define SM_V0    44288     // 2 x (32 x 136 fp16) [key][dh]    17408 B
#define SM_P     61696     // 64 x 40 fp16 (PSTR=80)            5120 B
#define SMEM_TOTAL 66816

#define QSTR 272
#define KSTR 272
#define VSTR 272
#define PSTR 80
#define KVBUF 8704

// ---------------------------------------------------------------------------
// mma.sync m16n8k16 fp16 (row.col), fp32 accum — valid on plain sm_103
// ---------------------------------------------------------------------------
#define MMA16816(d, a, b0_, b1_) \
  asm volatile("mma.sync.aligned.m16n8k16.row.col.f32.f16.f16.f32 " \
    "{%0,%1,%2,%3}, {%4,%5,%6,%7}, {%8,%9}, {%0,%1,%2,%3};" \
    : "+f"((d)[0]), "+f"((d)[1]), "+f"((d)[2]), "+f"((d)[3]) \
    : "r"((a)[0]), "r"((a)[1]), "r"((a)[2]), "r"((a)[3]), "r"(b0_), "r"(b1_))

#define LDSM_X4(R, ADDR) \
  asm volatile("ldmatrix.sync.aligned.m8n8.x4.shared.b16 {%0,%1,%2,%3}, [%4];" \
    : "=r"((R)[0]), "=r"((R)[1]), "=r"((R)[2]), "=r"((R)[3]) : "r"(ADDR))

#define LDSM_X4_T(R, ADDR) \
  asm volatile("ldmatrix.sync.aligned.m8n8.x4.trans.shared.b16 {%0,%1,%2,%3}, [%4];" \
    : "=r"((R)[0]), "=r"((R)[1]), "=r"((R)[2]), "=r"((R)[3]) : "r"(ADDR))

__device__ __forceinline__ uint32_t smem_u32(const void* p) {
  uint32_t a;
  asm("{ .reg .u64 t; cvta.to.shared.u64 t, %1; cvt.u32.u64 %0, t; }"
      : "=r"(a) : "l"(p));
  return a;
}
__device__ __forceinline__ uint32_t pkh2(float a, float b) {
  __half2 t = __floats2half2_rn(a, b);
  return *reinterpret_cast<uint32_t*>(&t);
}
__device__ __forceinline__ uint2 cvt4h(float4 v) {
  uint2 r;
  r.x = pkh2(v.x, v.y);
  r.y = pkh2(v.z, v.w);
  return r;
}

// ---------------------------------------------------------------------------
// Main kernel: one CTA per (batch, 64-q tile). 256 threads = 8 warps.
// 2 CTAs co-resident per SM; fused tail self-normalization of attention.
// ---------------------------------------------------------------------------
__global__ void __launch_bounds__(NTHR, 2)
gpa_main_kernel(const float* __restrict__ Q, const float* __restrict__ K,
                const float* __restrict__ V, const float* __restrict__ phases,
                float* __restrict__ out, float* __restrict__ attn,
                int write_attn) {
  extern __shared__ char smem[];
  const uint32_t sb = smem_u32(smem);
  const int tid = threadIdx.x;
  const int wid = tid >> 5;
  const int lane = tid & 31;
  const int g = lane >> 2;       // fragment row group 0..7
  const int c = lane & 3;        // fragment col group 0..3
  const int wm = wid >> 2;       // 0..1 : 32-q-row band
  const int wn = wid & 3;        // 0..3 : QK 8-key stripe / PV 32-dh stripe
  const int m = lane >> 3;       // ldmatrix matrix index 0..3
  const int rr = lane & 7;       // ldmatrix row within matrix

  const int b = blockIdx.y;
  const int q0 = blockIdx.x * QT;
  const float* Qb = Q + ((size_t)b * NQS + q0) * DHD;
  const float* Kb = K + (size_t)b * NKS * DHD;
  const float* Vb = V + (size_t)b * NKS * DHD;

  float* gate_s = (float*)(smem + SM_GATE);
  float* rsbuf  = (float*)(smem + SM_RS);
  float* rsp    = (float*)(smem + SM_RSP);

  // ldmatrix lane base addresses
  // Q A-frag: 16q x 16dh per x4 (matrices: row0-7,row8-15 x dh0-7,dh8-15)
  const uint32_t aQ0 = sb + SM_Q + (uint32_t)(wm*32 + (m&1)*8 + rr) * QSTR + (m>>1)*16;
  const uint32_t aQ1 = aQ0 + 16 * QSTR;
  // K B-frag: 8 keys x 32dh per x4 (4 dh-chunks of 8 for rows wn*8..+8)
  const uint32_t bKb = sb + SM_K0 + (uint32_t)(wn*8 + rr) * KSTR + m*16;
  // P A-frag: 16q x 16k per x4
  const uint32_t aP0 = sb + SM_P + (uint32_t)(wm*32 + (m&1)*8 + rr) * PSTR + (m>>1)*16;
  const uint32_t aP1 = aP0 + 16 * PSTR;
  // V B-frag (trans): 16k x 16dh per x4_T; dh stripe = wn*32
  const uint32_t vBb = sb + SM_V0 + (uint32_t)((m&1)*8 + rr) * VSTR
                       + (uint32_t)(wn*64) + (m>>1)*16;

  // --- gate precompute (includes 1/sqrt(dh)) ---
  for (int k = tid; k < NKS; k += NTHR) {
    float ph = phases[k];
    float pd = fminf(ph, TWO_PI_F - ph);
    gate_s[k] = __expf(-pd * pd * INV2W2_F) * SCALE_F;
  }

  // --- prefetch first K/V tile (32 keys x 128 dh = 1024 float4) ---
  const float4* kp4 = (const float4*)Kb;
  const float4* vp4 = (const float4*)Vb;
  float4 pfk[4], pfv[4];
#pragma unroll
  for (int t = 0; t < 4; t++) {
    pfk[t] = kp4[tid + t * NTHR];
    pfv[t] = vp4[tid + t * NTHR];
  }

  // --- Q tile -> SMEM fp16 (64 x 128) ---
  {
    const float4* qp = (const float4*)Qb;
#pragma unroll
    for (int t = 0; t < 8; t++) {
      int it = tid + t * NTHR;
      int row = it >> 5;
      int c4 = (it & 31) << 2;
      *(uint2*)(smem + SM_Q + row * QSTR + c4 * 2) = cvt4h(qp[it]);
    }
  }

  // --- store tile 0 into K/V buffer 0 ---
#pragma unroll
  for (int t = 0; t < 4; t++) {
    int it = tid + t * NTHR;
    int row = it >> 5;
    int c4 = (it & 31) << 2;
    int off = row * KSTR + c4 * 2;
    *(uint2*)(smem + SM_K0 + off) = cvt4h(pfk[t]);
    *(uint2*)(smem + SM_V0 + off) = cvt4h(pfv[t]);
  }
  __syncthreads();

  float o[2][4][4];   // persistent O accumulators: 32 q x 32 dh per warp
#pragma unroll
  for (int i = 0; i < 2; i++)
#pragma unroll
    for (int j = 0; j < 4; j++)
#pragma unroll
      for (int e = 0; e < 4; e++) o[i][j][e] = 0.0f;

  float rs[2][2] = {{0.f,0.f},{0.f,0.f}};

  for (int kt = 0; kt < NIT; kt++) {
    const int k0 = kt * KT;
    const uint32_t bufo = (uint32_t)(kt & 1) * KVBUF;

    // --- issue next tile's LDG (hidden behind QK + epilogue + PV) ---
    if (kt < NIT - 1) {
      int base = (kt + 1) * 1024;
#pragma unroll
      for (int t = 0; t < 4; t++) {
        pfk[t] = kp4[base + tid + t * NTHR];
        pfv[t] = vp4[base + tid + t * NTHR];
      }
    }

    // --- S = Q K^T  (warp tile 32q x 8k, single-pass fp16) ---
    float s[2][4];
    s[0][0]=s[0][1]=s[0][2]=s[0][3]=0.f;
    s[1][0]=s[1][1]=s[1][2]=s[1][3]=0.f;

#pragma unroll
    for (int kc2 = 0; kc2 < 4; kc2++) {      // 32 dh per pass
      uint32_t a0[4], a1[4], bk[4];
      const uint32_t ko = kc2 * 64;
      LDSM_X4(bk, bKb + bufo + ko);
      LDSM_X4(a0, aQ0 + ko);
      LDSM_X4(a1, aQ1 + ko);
      MMA16816(s[0], a0, bk[0], bk[1]);
      MMA16816(s[1], a1, bk[0], bk[1]);
      LDSM_X4(a0, aQ0 + ko + 32);
      LDSM_X4(a1, aQ1 + ko + 32);
      MMA16816(s[0], a0, bk[2], bk[3]);
      MMA16816(s[1], a1, bk[2], bk[3]);
    }

    // --- Epilogue: p = exp(s*gate); rowsum; P fp16 -> SMEM; attn STG ---
#pragma unroll
    for (int i = 0; i < 2; i++) {
      const int lr = wm*32 + i*16 + g;
      const int lc = wn*8 + 2*c;
      float2 gt = *(const float2*)(smem + SM_GATE + (size_t)(k0 + lc) * 4);
      float p00 = __expf(s[i][0] * gt.x);
      float p01 = __expf(s[i][1] * gt.y);
      float p10 = __expf(s[i][2] * gt.x);
      float p11 = __expf(s[i][3] * gt.y);
      rs[i][0] += p00 + p01;
      rs[i][1] += p10 + p11;
      int po = lr * PSTR + lc * 2;
      *(uint32_t*)(smem + SM_P + po)          = pkh2(p00, p01);
      *(uint32_t*)(smem + SM_P + po + 8*PSTR) = pkh2(p10, p11);
      if (write_attn) {
        float* a0 = attn + ((size_t)(b * NQS + q0 + lr)) * NKS + (k0 + lc);
        *(float2*)a0 = make_float2(p00, p01);
        *(float2*)(a0 + (size_t)8 * NKS) = make_float2(p10, p11);
      }
    }
    __syncthreads();   // P visible to all warps

    // --- store next K/V tile into the other buffer (overlaps PV) ---
    if (kt < NIT - 1) {
      const uint32_t nb = (uint32_t)((kt + 1) & 1) * KVBUF;
#pragma unroll
      for (int t = 0; t < 4; t++) {
        int it = tid + t * NTHR;
        int row = it >> 5;
        int c4 = (it & 31) << 2;
        int off = row * KSTR + c4 * 2;
        *(uint2*)(smem + SM_K0 + nb + off) = cvt4h(pfk[t]);
        *(uint2*)(smem + SM_V0 + nb + off) = cvt4h(pfv[t]);
      }
    }

    // --- O += P V  (warp tile 32q x 32dh, 32 keys, single-pass fp16) ---
#pragma unroll
    for (int kc = 0; kc < 2; kc++) {         // 16 keys per pass
      uint32_t p0[4], p1[4], v0[4], v1[4];
      const uint32_t po = kc * 32;
      const uint32_t vo = bufo + kc * 16 * VSTR;
      LDSM_X4(p0, aP0 + po);
      LDSM_X4(p1, aP1 + po);
      LDSM_X4_T(v0, vBb + vo);
      LDSM_X4_T(v1, vBb + vo + 32);
      MMA16816(o[0][0], p0, v0[0], v0[1]);
      MMA16816(o[1][0], p1, v0[0], v0[1]);
      MMA16816(o[0][1], p0, v0[2], v0[3]);
      MMA16816(o[1][1], p1, v0[2], v0[3]);
      MMA16816(o[0][2], p0, v1[0], v1[1]);
      MMA16816(o[1][2], p1, v1[0], v1[1]);
      MMA16816(o[0][3], p0, v1[2], v1[3]);
      MMA16816(o[1][3], p1, v1[2], v1[3]);
    }
    __syncthreads();   // K/V/P consumed; next iteration may overwrite
  }

  // --- Rowsum: quad shfl -> per-wn partials -> deterministic 4-way combine ---
#pragma unroll
  for (int i = 0; i < 2; i++)
#pragma unroll
    for (int h = 0; h < 2; h++) {
      float v = rs[i][h];
      v += __shfl_xor_sync(0xffffffffu, v, 1);
      v += __shfl_xor_sync(0xffffffffu, v, 2);
      rs[i][h] = v;
    }
  if (c == 0) {
#pragma unroll
    for (int i = 0; i < 2; i++)
#pragma unroll
      for (int h = 0; h < 2; h++)
        rsp[wn * 64 + wm*32 + i*16 + h*8 + g] = rs[i][h];
  }
  __syncthreads();
  if (tid < 64) {
    float rsum = (rsp[tid] + rsp[64 + tid]) + (rsp[128 + tid] + rsp[192 + tid]);
    rsbuf[tid] = 1.0f / rsum;
  }
  __syncthreads();   // rsbuf ready; orders this CTA's attn STG before reads

  // --- Normalized output store (each warp: 32q x 32dh) ---
#pragma unroll
  for (int i = 0; i < 2; i++) {
    const int lr = wm*32 + i*16 + g;
    const float inv0 = rsbuf[lr];
    const float inv1 = rsbuf[lr + 8];
    float* o0 = out + ((size_t)(b * NQS + q0 + lr)) * DHD + wn*32 + 2*c;
#pragma unroll
    for (int j = 0; j < 4; j++) {
      *(float2*)(o0 + j*8) = make_float2(o[i][j][0] * inv0, o[i][j][1] * inv0);
      *(float2*)(o0 + (size_t)8 * DHD + j*8) =
          make_float2(o[i][j][2] * inv1, o[i][j][3] * inv1);
    }
  }

  // --- Self-normalize this CTA's 64 x 2048 attention block ---
  if (write_attn) {
    float4* a4 = (float4*)(attn + ((size_t)(b * NQS + q0)) * NKS);
#pragma unroll 4
    for (int it = tid; it < 32768; it += NTHR) {
      const float inv = rsbuf[it >> 9];   // 512 float4 per row
      float4 v = a4[it];
      v.x *= inv; v.y *= inv; v.z *= inv; v.w *= inv;
      a4[it] = v;
    }
  }
}

// ---------------------------------------------------------------------------
// Launch
// ---------------------------------------------------------------------------
extern "C" void kernel_launch(void* const* d_in, const int* in_sizes, int n_in,
                              void* d_out, int out_size) {
  const float* Q  = (const float*)d_in[0];
  const float* K  = (const float*)d_in[1];
  const float* V  = (const float*)d_in[2];
  const float* ph = (const float*)d_in[3];
  float* out = (float*)d_out;

  const bool write_attn = ((long long)out_size >= (long long)OUT_ELEMS + ATTN_ELEMS);
  float* attn = out + OUT_ELEMS;

  cudaFuncSetAttribute(gpa_main_kernel,
                       cudaFuncAttributeMaxDynamicSharedMemorySize, SMEM_TOTAL);

  dim3 grid(NQS / QT, BB);
  gpa_main_kernel<<<grid, NTHR, SMEM_TOTAL>>>(Q, K, V, ph, out, attn,
                                              write_attn ? 1 : 0);
}